// round 1
// baseline (speedup 1.0000x reference)
#include <cuda_runtime.h>

// Problem geometry (fixed by reference)
#define Hh 16
#define Bb 4
#define Ss 1024
#define Dd 1024
#define dhd 64
#define LN_EPS 1e-5f

// Scratch (allocation-free rule: __device__ globals)
__device__ float g_Q[Bb * Ss * Dd];
__device__ float g_K[Bb * Ss * Dd];
__device__ float g_V[Bb * Ss * Dd];
__device__ float g_concat[Bb * Ss * Dd];
__device__ float g_pre[Bb * Ss * Dd];

// ---------------------------------------------------------------------------
// Generic batched SGEMM:  C[h,b] = alpha * A[h,b] @ op(B[h,b]) (+ R)
//   TB=false: B is [K,N] row-major. TB=true: B is [N,K] row-major (C = A B^T).
//   Batch index z decomposes as h = z/NB, b = z%NB; per-dim offsets sXh/sXb.
// 128x128x16 (256 thr) or 128x64x16 (128 thr), 8x8 per-thread microtile.
// ---------------------------------------------------------------------------
template <int BM, int BN, int BK, bool TB, int NB>
__global__ __launch_bounds__((BM / 8) * (BN / 8))
void gemm_k(const float* __restrict__ A, int lda, long long sAh, long long sAb,
            const float* __restrict__ B, int ldb, long long sBh, long long sBb,
            float* __restrict__ C, int ldc, long long sCh, long long sCb,
            const float* __restrict__ R,
            int M, int N, int K, float alpha)
{
    constexpr int TM = 8, TN = 8;
    constexpr int NT = (BM / TM) * (BN / TN);

    const int z = blockIdx.z;
    const int h = z / NB;
    const int b = z % NB;
    const float* Ap = A + h * sAh + b * sAb;
    const float* Bp = B + h * sBh + b * sBb;
    float*       Cp = C + h * sCh + b * sCb;

    __shared__ float As[BK][BM];
    __shared__ float Bs[BK][BN];

    const int tid = threadIdx.x;
    const int tx = tid % (BN / TN);
    const int ty = tid / (BN / TN);
    const int rowBase = blockIdx.y * BM;
    const int colBase = blockIdx.x * BN;

    float acc[TM][TN] = {};

    for (int k0 = 0; k0 < K; k0 += BK) {
        // ---- load A tile [BM][BK], store transposed As[k][m]
        constexpr int AV = (BM * BK / 4) / NT;
        #pragma unroll
        for (int t = 0; t < AV; t++) {
            int i = tid + t * NT;
            int r = (i * 4) / BK, c = (i * 4) % BK;
            float4 v = *(const float4*)(Ap + (long long)(rowBase + r) * lda + k0 + c);
            As[c + 0][r] = v.x; As[c + 1][r] = v.y;
            As[c + 2][r] = v.z; As[c + 3][r] = v.w;
        }
        // ---- load B tile
        if (!TB) {
            constexpr int BV = (BK * BN / 4) / NT;
            #pragma unroll
            for (int t = 0; t < BV; t++) {
                int i = tid + t * NT;
                int r = (i * 4) / BN, c = (i * 4) % BN;
                *(float4*)&Bs[r][c] =
                    *(const float4*)(Bp + (long long)(k0 + r) * ldb + colBase + c);
            }
        } else {
            constexpr int BV = (BN * BK / 4) / NT;
            #pragma unroll
            for (int t = 0; t < BV; t++) {
                int i = tid + t * NT;
                int r = (i * 4) / BK, c = (i * 4) % BK;  // r = n index, c = k
                float4 v = *(const float4*)(Bp + (long long)(colBase + r) * ldb + k0 + c);
                Bs[c + 0][r] = v.x; Bs[c + 1][r] = v.y;
                Bs[c + 2][r] = v.z; Bs[c + 3][r] = v.w;
            }
        }
        __syncthreads();

        #pragma unroll
        for (int k = 0; k < BK; k++) {
            float ra[TM], rb[TN];
            #pragma unroll
            for (int i = 0; i < TM; i++) ra[i] = As[k][ty * TM + i];
            #pragma unroll
            for (int j = 0; j < TN; j++) rb[j] = Bs[k][tx * TN + j];
            #pragma unroll
            for (int i = 0; i < TM; i++)
                #pragma unroll
                for (int j = 0; j < TN; j++)
                    acc[i][j] = fmaf(ra[i], rb[j], acc[i][j]);
        }
        __syncthreads();
    }

    // ---- epilogue: alpha scale, optional residual add, float4 stores
    #pragma unroll
    for (int i = 0; i < TM; i++) {
        long long off = (long long)(rowBase + ty * TM + i) * ldc + colBase + tx * TN;
        #pragma unroll
        for (int j = 0; j < TN; j += 4) {
            float4 v;
            v.x = acc[i][j + 0] * alpha;
            v.y = acc[i][j + 1] * alpha;
            v.z = acc[i][j + 2] * alpha;
            v.w = acc[i][j + 3] * alpha;
            if (R) {
                float4 r4 = *(const float4*)(R + off + j);
                v.x += r4.x; v.y += r4.y; v.z += r4.z; v.w += r4.w;
            }
            *(float4*)(Cp + off + j) = v;
        }
    }
}

// ---------------------------------------------------------------------------
// In-place causal softmax over rows of length 1024.
// Row index = (h*Bb + b)*Ss + q. Valid region j <= q; rest written as 0.
// (Reference's softmax -> zero-triu -> renormalize == causal softmax.)
// ---------------------------------------------------------------------------
__global__ void softmax_causal_k(float* __restrict__ A)
{
    const long long row = blockIdx.x;
    const int q = (int)(row & (Ss - 1));
    float* p = A + (row << 10);
    const int tid = threadIdx.x;  // 256 threads, float4 each -> 1024

    float4 v = reinterpret_cast<const float4*>(p)[tid];
    const int j0 = tid * 4;

    float m = -3.4e38f;
    if (j0 + 0 <= q) m = fmaxf(m, v.x);
    if (j0 + 1 <= q) m = fmaxf(m, v.y);
    if (j0 + 2 <= q) m = fmaxf(m, v.z);
    if (j0 + 3 <= q) m = fmaxf(m, v.w);

    __shared__ float red[8];
    #pragma unroll
    for (int o = 16; o; o >>= 1) m = fmaxf(m, __shfl_xor_sync(0xffffffffu, m, o));
    if ((tid & 31) == 0) red[tid >> 5] = m;
    __syncthreads();
    m = red[0];
    #pragma unroll
    for (int i = 1; i < 8; i++) m = fmaxf(m, red[i]);
    __syncthreads();

    float e0 = (j0 + 0 <= q) ? __expf(v.x - m) : 0.f;
    float e1 = (j0 + 1 <= q) ? __expf(v.y - m) : 0.f;
    float e2 = (j0 + 2 <= q) ? __expf(v.z - m) : 0.f;
    float e3 = (j0 + 3 <= q) ? __expf(v.w - m) : 0.f;

    float s = e0 + e1 + e2 + e3;
    #pragma unroll
    for (int o = 16; o; o >>= 1) s += __shfl_xor_sync(0xffffffffu, s, o);
    if ((tid & 31) == 0) red[tid >> 5] = s;
    __syncthreads();
    s = red[0];
    #pragma unroll
    for (int i = 1; i < 8; i++) s += red[i];

    const float inv = 1.0f / s;
    float4 o4;
    o4.x = e0 * inv; o4.y = e1 * inv; o4.z = e2 * inv; o4.w = e3 * inv;
    reinterpret_cast<float4*>(p)[tid] = o4;
}

// ---------------------------------------------------------------------------
// Row LayerNorm: out = (x - mu) / sqrt(var + eps) * gamma + beta
// One block (256 thr) per 1024-wide row.
// ---------------------------------------------------------------------------
__global__ void layernorm_k(const float* __restrict__ X,
                            const float* __restrict__ gamma,
                            const float* __restrict__ beta,
                            float* __restrict__ O)
{
    const long long row = blockIdx.x;
    const int tid = threadIdx.x;
    const float4 v = reinterpret_cast<const float4*>(X + (row << 10))[tid];

    float s  = v.x + v.y + v.z + v.w;
    float s2 = v.x * v.x + v.y * v.y + v.z * v.z + v.w * v.w;

    __shared__ float r1[8], r2[8];
    #pragma unroll
    for (int o = 16; o; o >>= 1) {
        s  += __shfl_xor_sync(0xffffffffu, s, o);
        s2 += __shfl_xor_sync(0xffffffffu, s2, o);
    }
    if ((tid & 31) == 0) { r1[tid >> 5] = s; r2[tid >> 5] = s2; }
    __syncthreads();
    s = 0.f; s2 = 0.f;
    #pragma unroll
    for (int i = 0; i < 8; i++) { s += r1[i]; s2 += r2[i]; }

    const float mean = s * (1.0f / Dd);
    const float var  = s2 * (1.0f / Dd) - mean * mean;
    const float rstd = rsqrtf(var + LN_EPS);

    const float4 g = reinterpret_cast<const float4*>(gamma)[tid];
    const float4 be = reinterpret_cast<const float4*>(beta)[tid];
    float4 o4;
    o4.x = (v.x - mean) * rstd * g.x + be.x;
    o4.y = (v.y - mean) * rstd * g.y + be.y;
    o4.z = (v.z - mean) * rstd * g.z + be.z;
    o4.w = (v.w - mean) * rstd * g.w + be.w;
    reinterpret_cast<float4*>(O + (row << 10))[tid] = o4;
}

// ---------------------------------------------------------------------------
extern "C" void kernel_launch(void* const* d_in, const int* in_sizes, int n_in,
                              void* d_out, int out_size)
{
    const float* query = (const float*)d_in[0];
    const float* key   = (const float*)d_in[1];
    const float* value = (const float*)d_in[2];
    const float* Wq    = (const float*)d_in[3];
    const float* Wk    = (const float*)d_in[4];
    const float* Wv    = (const float*)d_in[5];
    const float* Wo    = (const float*)d_in[6];
    const float* gamma = (const float*)d_in[7];
    const float* beta  = (const float*)d_in[8];

    float* out  = (float*)d_out;                       // [B,S,D]
    float* attn = out + (long long)Bb * Ss * Dd;       // [H,B,S,S]

    float *Qb, *Kb, *Vb, *Cc, *Pre;
    cudaGetSymbolAddress((void**)&Qb,  g_Q);
    cudaGetSymbolAddress((void**)&Kb,  g_K);
    cudaGetSymbolAddress((void**)&Vb,  g_V);
    cudaGetSymbolAddress((void**)&Cc,  g_concat);
    cudaGetSymbolAddress((void**)&Pre, g_pre);

    const long long sSD = (long long)Ss * Dd;   // per-batch stride of [B*S, D] mats
    const long long sSS = (long long)Ss * Ss;   // per-(h,b) stride of attn

    // 1-3. QKV projections: [4096,1024] @ [1024,1024]
    gemm_k<128, 128, 16, false, 1><<<dim3(Dd / 128, (Bb * Ss) / 128, 1), 256>>>(
        query, Dd, 0, 0, Wq, Dd, 0, 0, Qb, Dd, 0, 0, nullptr, Bb * Ss, Dd, Dd, 1.f);
    gemm_k<128, 128, 16, false, 1><<<dim3(Dd / 128, (Bb * Ss) / 128, 1), 256>>>(
        key,   Dd, 0, 0, Wk, Dd, 0, 0, Kb, Dd, 0, 0, nullptr, Bb * Ss, Dd, Dd, 1.f);
    gemm_k<128, 128, 16, false, 1><<<dim3(Dd / 128, (Bb * Ss) / 128, 1), 256>>>(
        value, Dd, 0, 0, Wv, Dd, 0, 0, Vb, Dd, 0, 0, nullptr, Bb * Ss, Dd, Dd, 1.f);

    // 4. scores = Q K^T / 8, batched over (h,b), written straight into attn region
    gemm_k<128, 128, 16, true, Bb><<<dim3(Ss / 128, Ss / 128, Hh * Bb), 256>>>(
        Qb, Dd, dhd, sSD,
        Kb, Dd, dhd, sSD,
        attn, Ss, (long long)Bb * sSS, sSS,
        nullptr, Ss, Ss, dhd, 0.125f);

    // 5. causal softmax in-place (writes zeros above diagonal)
    softmax_causal_k<<<Hh * Bb * Ss, 256>>>(attn);

    // 6. ws = attn @ V, written head-interleaved into concat [B,S,D]
    gemm_k<128, 64, 16, false, Bb><<<dim3(1, Ss / 128, Hh * Bb), 128>>>(
        attn, Ss, (long long)Bb * sSS, sSS,
        Vb, Dd, dhd, sSD,
        Cc, Dd, dhd, sSD,
        nullptr, Ss, dhd, Ss, 1.f);

    // 7. out-proj + residual: pre = concat @ Wo + query
    gemm_k<128, 128, 16, false, 1><<<dim3(Dd / 128, (Bb * Ss) / 128, 1), 256>>>(
        Cc, Dd, 0, 0, Wo, Dd, 0, 0, Pre, Dd, 0, 0, query, Bb * Ss, Dd, Dd, 1.f);

    // 8. LayerNorm -> out
    layernorm_k<<<Bb * Ss, 256>>>(Pre, gamma, beta, out);
}

// round 3
// speedup vs baseline: 3.4035x; 3.4035x over previous
#include <cuda_runtime.h>
#include <cstdint>

#define Hh 16
#define Bb 4
#define Ss 1024
#define Dd 1024
#define dhd 64
#define LN_EPS 1e-5f

// Scratch (__device__ globals; allocation-free rule)
__device__ float g_Q[Bb * Ss * Dd];
__device__ float g_K[Bb * Ss * Dd];
__device__ float g_V[Bb * Ss * Dd];
__device__ float g_Vt[Hh * Bb * dhd * Ss];   // V^T per (h,b): [64][1024] K-contig
__device__ float g_concat[Bb * Ss * Dd];
__device__ float g_pre[Bb * Ss * Dd];
__device__ float g_WT[4 * Dd * Dd];          // WqT,WkT,WvT,WoT ([N][K] K-contig)

// ---------------------------------------------------------------------------
// Portable (non-'a') PTX helpers: cp.async (sm_80), mma.sync tf32 (sm_80)
// ---------------------------------------------------------------------------
__device__ __forceinline__ void cp16(uint32_t dst, const float* src) {
    uint64_t g = __cvta_generic_to_global((void*)src);
    asm volatile("cp.async.cg.shared.global [%0], [%1], 16;" :: "r"(dst), "l"(g));
}
__device__ __forceinline__ uint32_t smem_u32(const void* p) {
    uint32_t a;
    asm("{ .reg .u64 t; cvta.to.shared.u64 t, %1; cvt.u32.u64 %0, t; }" : "=r"(a) : "l"(p));
    return a;
}
__device__ __forceinline__ uint32_t tf32u(float x) {
    float r;
    asm("cvt.rna.tf32.f32 %0, %1;" : "=f"(r) : "f"(x));
    return __float_as_uint(r);
}
__device__ __forceinline__ void mma8(float* c, const uint32_t* a, const uint32_t* b) {
    asm volatile(
        "mma.sync.aligned.m16n8k8.row.col.f32.tf32.tf32.f32 "
        "{%0,%1,%2,%3}, {%4,%5,%6,%7}, {%8,%9}, {%0,%1,%2,%3};"
        : "+f"(c[0]), "+f"(c[1]), "+f"(c[2]), "+f"(c[3])
        : "r"(a[0]), "r"(a[1]), "r"(a[2]), "r"(a[3]), "r"(b[0]), "r"(b[1]));
}

// ---------------------------------------------------------------------------
// tf32 mma.sync GEMM:  C = alpha * A @ B^T  (+R)
//   A: [M][K] K-contig (lda), B: [N][K] K-contig (ldb). BK=16 per chunk.
// MODE 0: plain,     grid(N/128, M/128)
// MODE 1: causal scores tiles,  grid(36, 1, 64)   alpha=0.125
// MODE 2: PV, causal K-length,  grid(8, 1, 64)    BN=64
// 256 threads = 8 warps. BN=128: warps 2x4 (64x32 each). BN=64: 4x2 (32x32).
// ---------------------------------------------------------------------------
template <int BM, int BN, int MODE>
__global__ __launch_bounds__(256)
void mma_gemm(const float* __restrict__ A, int lda,
              const float* __restrict__ Bm, int ldb,
              float* __restrict__ Cm, int ldc,
              const float* __restrict__ R, float alpha, int NCin)
{
    constexpr int WN_ = 32;
    constexpr int WM_ = (BN == 128) ? 64 : 32;
    constexpr int WARPS_N = BN / WN_;          // 4 or 2
    constexpr int MT = WM_ / 16, NT = WN_ / 8; // (4,4) or (2,4)
    constexpr int PAD = 20;                     // floats per row (16 + 4 pad)

    __shared__ float sA[2][BM * PAD];
    __shared__ float sB[2][BN * PAD];

    const int tid = threadIdx.x, w = tid >> 5, lane = tid & 31;
    const int wm = w / WARPS_N, wn = w % WARPS_N;
    const int g = lane >> 2, tq = lane & 3;

    // ---- operand bases per mode
    const float* Ap; const float* Bp; float* Cp; const float* Rp = nullptr;
    int NC;
    if constexpr (MODE == 1) {
        int idx = blockIdx.x, qt = 0;
        while (idx >= ((qt + 1) * (qt + 2)) / 2) qt++;
        const int kt = idx - (qt * (qt + 1)) / 2;
        const int z = blockIdx.z, h = z >> 2, b = z & 3;
        Ap = A + ((long long)b * Ss + qt * 128) * Dd + h * dhd;
        Bp = Bm + ((long long)b * Ss + kt * 128) * Dd + h * dhd;
        Cp = Cm + (long long)z * Ss * Ss + (long long)(qt * 128) * Ss + kt * 128;
        NC = 4;
    } else if constexpr (MODE == 2) {
        const int qt = blockIdx.x, z = blockIdx.z, h = z >> 2, b = z & 3;
        Ap = A + (long long)z * Ss * Ss + (long long)(qt * 128) * Ss;
        Bp = Bm + (long long)z * dhd * Ss;
        Cp = Cm + ((long long)b * Ss + qt * 128) * Dd + h * dhd;
        NC = (qt + 1) * 8;
    } else {
        Ap = A + (long long)blockIdx.y * 128 * lda;
        Bp = Bm + (long long)blockIdx.x * 128 * ldb;
        Cp = Cm + (long long)blockIdx.y * 128 * ldc + blockIdx.x * 128;
        if (R) Rp = R + (long long)blockIdx.y * 128 * ldc + blockIdx.x * 128;
        NC = NCin;
    }

    const uint32_t sA0 = smem_u32(&sA[0][0]), sA1 = smem_u32(&sA[1][0]);
    const uint32_t sB0 = smem_u32(&sB[0][0]), sB1 = smem_u32(&sB[1][0]);

    auto loadc = [&](int c, int p) {
        const float* a = Ap + c * 16;
        const uint32_t da = p ? sA1 : sA0;
        #pragma unroll
        for (int i = 0; i < BM * 4 / 256; i++) {
            int idx = tid + i * 256, row = idx >> 2, kq = idx & 3;
            cp16(da + (uint32_t)(row * PAD + kq * 4) * 4, a + (long long)row * lda + kq * 4);
        }
        const float* b = Bp + c * 16;
        const uint32_t db = p ? sB1 : sB0;
        #pragma unroll
        for (int i = 0; i < BN * 4 / 256; i++) {
            int idx = tid + i * 256, row = idx >> 2, kq = idx & 3;
            cp16(db + (uint32_t)(row * PAD + kq * 4) * 4, b + (long long)row * ldb + kq * 4);
        }
        asm volatile("cp.async.commit_group;" ::: "memory");
    };

    float acc[MT][NT][4];
    #pragma unroll
    for (int i = 0; i < MT; i++)
        #pragma unroll
        for (int j = 0; j < NT; j++)
            acc[i][j][0] = acc[i][j][1] = acc[i][j][2] = acc[i][j][3] = 0.f;

    loadc(0, 0);
    for (int c = 0; c < NC; c++) {
        const int p = c & 1;
        if (c + 1 < NC) {
            loadc(c + 1, p ^ 1);
            asm volatile("cp.async.wait_group 1;" ::: "memory");
        } else {
            asm volatile("cp.async.wait_group 0;" ::: "memory");
        }
        __syncthreads();

        const float* Asr = sA[p];
        const float* Bsr = sB[p];
        #pragma unroll
        for (int ks = 0; ks < 2; ks++) {
            const int k = ks * 8 + tq;
            uint32_t afr[MT][4], bfr[NT][2];
            #pragma unroll
            for (int mt = 0; mt < MT; mt++) {
                const int r = wm * WM_ + mt * 16 + g;
                afr[mt][0] = tf32u(Asr[r * PAD + k]);
                afr[mt][1] = tf32u(Asr[(r + 8) * PAD + k]);
                afr[mt][2] = tf32u(Asr[r * PAD + k + 4]);
                afr[mt][3] = tf32u(Asr[(r + 8) * PAD + k + 4]);
            }
            #pragma unroll
            for (int nt = 0; nt < NT; nt++) {
                const int n = wn * WN_ + nt * 8 + g;
                bfr[nt][0] = tf32u(Bsr[n * PAD + k]);
                bfr[nt][1] = tf32u(Bsr[n * PAD + k + 4]);
            }
            #pragma unroll
            for (int mt = 0; mt < MT; mt++)
                #pragma unroll
                for (int nt = 0; nt < NT; nt++)
                    mma8(acc[mt][nt], afr[mt], bfr[nt]);
        }
        __syncthreads();
    }

    // ---- epilogue: c0,c1 -> row g, cols 2tq..; c2,c3 -> row g+8
    #pragma unroll
    for (int mt = 0; mt < MT; mt++) {
        #pragma unroll
        for (int nt = 0; nt < NT; nt++) {
            const int r = wm * WM_ + mt * 16 + g;
            const int cc = wn * WN_ + nt * 8 + 2 * tq;
            float2 v0 = make_float2(acc[mt][nt][0] * alpha, acc[mt][nt][1] * alpha);
            float2 v1 = make_float2(acc[mt][nt][2] * alpha, acc[mt][nt][3] * alpha);
            if (MODE == 0 && Rp) {
                float2 r0 = *(const float2*)(Rp + (long long)r * ldc + cc);
                float2 r1 = *(const float2*)(Rp + (long long)(r + 8) * ldc + cc);
                v0.x += r0.x; v0.y += r0.y; v1.x += r1.x; v1.y += r1.y;
            }
            *(float2*)(Cp + (long long)r * ldc + cc) = v0;
            *(float2*)(Cp + (long long)(r + 8) * ldc + cc) = v1;
        }
    }
}

// ---------------------------------------------------------------------------
// Weight transposes -> [N][K] K-contig
// ---------------------------------------------------------------------------
__global__ void transpose_w_k(const float* __restrict__ W0, const float* __restrict__ W1,
                              const float* __restrict__ W2, const float* __restrict__ W3,
                              float* __restrict__ O)
{
    __shared__ float t[32][33];
    const float* W = blockIdx.z == 0 ? W0 : blockIdx.z == 1 ? W1 : blockIdx.z == 2 ? W2 : W3;
    float* Oz = O + (long long)blockIdx.z * Dd * Dd;
    const int x0 = blockIdx.x * 32, y0 = blockIdx.y * 32;
    const int tx = threadIdx.x, ty0 = threadIdx.y;
    #pragma unroll
    for (int j = 0; j < 4; j++) {
        int ty = ty0 + j * 8;
        t[ty][tx] = W[(long long)(y0 + ty) * Dd + x0 + tx];
    }
    __syncthreads();
    #pragma unroll
    for (int j = 0; j < 4; j++) {
        int ty = ty0 + j * 8;
        Oz[(long long)(x0 + ty) * Dd + y0 + tx] = t[tx][ty];
    }
}

// ---------------------------------------------------------------------------
// V [B][S][D] -> Vt [(h*Bb+b)*64 + n][S]
// ---------------------------------------------------------------------------
__global__ void transpose_v_k(const float* __restrict__ V, float* __restrict__ Vt)
{
    __shared__ float t[32][33];
    const int s0 = blockIdx.x * 32, d0 = blockIdx.y * 32, b = blockIdx.z;
    const int tx = threadIdx.x, ty0 = threadIdx.y;
    #pragma unroll
    for (int j = 0; j < 4; j++) {
        int ty = ty0 + j * 8;
        t[ty][tx] = V[((long long)b * Ss + s0 + ty) * Dd + d0 + tx];
    }
    __syncthreads();
    const int h = d0 >> 6, n0 = d0 & 63;
    #pragma unroll
    for (int j = 0; j < 4; j++) {
        int ty = ty0 + j * 8;
        Vt[((long long)(h * Bb + b) * dhd + n0 + ty) * Ss + s0 + tx] = t[tx][ty];
    }
}

// ---------------------------------------------------------------------------
// Causal softmax, in place. Tiles above the diagonal were never written by the
// scores GEMM, so loads are skipped there; zeros are written.
// ---------------------------------------------------------------------------
__global__ void softmax_causal_k(float* __restrict__ A)
{
    const long long row = blockIdx.x;
    const int q = (int)(row & (Ss - 1));
    float* p = A + (row << 10);
    const int tid = threadIdx.x;
    const int j0 = tid * 4;

    float4 v = make_float4(0.f, 0.f, 0.f, 0.f);
    if (j0 <= q) v = reinterpret_cast<const float4*>(p)[tid];

    float m = -3.4e38f;
    if (j0 + 0 <= q) m = fmaxf(m, v.x);
    if (j0 + 1 <= q) m = fmaxf(m, v.y);
    if (j0 + 2 <= q) m = fmaxf(m, v.z);
    if (j0 + 3 <= q) m = fmaxf(m, v.w);

    __shared__ float red[8];
    #pragma unroll
    for (int o = 16; o; o >>= 1) m = fmaxf(m, __shfl_xor_sync(0xffffffffu, m, o));
    if ((tid & 31) == 0) red[tid >> 5] = m;
    __syncthreads();
    m = red[0];
    #pragma unroll
    for (int i = 1; i < 8; i++) m = fmaxf(m, red[i]);
    __syncthreads();

    float e0 = (j0 + 0 <= q) ? __expf(v.x - m) : 0.f;
    float e1 = (j0 + 1 <= q) ? __expf(v.y - m) : 0.f;
    float e2 = (j0 + 2 <= q) ? __expf(v.z - m) : 0.f;
    float e3 = (j0 + 3 <= q) ? __expf(v.w - m) : 0.f;

    float s = e0 + e1 + e2 + e3;
    #pragma unroll
    for (int o = 16; o; o >>= 1) s += __shfl_xor_sync(0xffffffffu, s, o);
    if ((tid & 31) == 0) red[tid >> 5] = s;
    __syncthreads();
    s = red[0];
    #pragma unroll
    for (int i = 1; i < 8; i++) s += red[i];

    const float inv = 1.0f / s;
    reinterpret_cast<float4*>(p)[tid] = make_float4(e0 * inv, e1 * inv, e2 * inv, e3 * inv);
}

// ---------------------------------------------------------------------------
__global__ void layernorm_k(const float* __restrict__ X,
                            const float* __restrict__ gamma,
                            const float* __restrict__ beta,
                            float* __restrict__ O)
{
    const long long row = blockIdx.x;
    const int tid = threadIdx.x;
    const float4 v = reinterpret_cast<const float4*>(X + (row << 10))[tid];

    float s  = v.x + v.y + v.z + v.w;
    float s2 = v.x * v.x + v.y * v.y + v.z * v.z + v.w * v.w;

    __shared__ float r1[8], r2[8];
    #pragma unroll
    for (int o = 16; o; o >>= 1) {
        s  += __shfl_xor_sync(0xffffffffu, s, o);
        s2 += __shfl_xor_sync(0xffffffffu, s2, o);
    }
    if ((tid & 31) == 0) { r1[tid >> 5] = s; r2[tid >> 5] = s2; }
    __syncthreads();
    s = 0.f; s2 = 0.f;
    #pragma unroll
    for (int i = 0; i < 8; i++) { s += r1[i]; s2 += r2[i]; }

    const float mean = s * (1.0f / Dd);
    const float var  = s2 * (1.0f / Dd) - mean * mean;
    const float rstd = rsqrtf(var + LN_EPS);

    const float4 g  = reinterpret_cast<const float4*>(gamma)[tid];
    const float4 be = reinterpret_cast<const float4*>(beta)[tid];
    reinterpret_cast<float4*>(O + (row << 10))[tid] = make_float4(
        (v.x - mean) * rstd * g.x + be.x,
        (v.y - mean) * rstd * g.y + be.y,
        (v.z - mean) * rstd * g.z + be.z,
        (v.w - mean) * rstd * g.w + be.w);
}

// ---------------------------------------------------------------------------
extern "C" void kernel_launch(void* const* d_in, const int* in_sizes, int n_in,
                              void* d_out, int out_size)
{
    const float* query = (const float*)d_in[0];
    const float* key   = (const float*)d_in[1];
    const float* value = (const float*)d_in[2];
    const float* Wq    = (const float*)d_in[3];
    const float* Wk    = (const float*)d_in[4];
    const float* Wv    = (const float*)d_in[5];
    const float* Wo    = (const float*)d_in[6];
    const float* gamma = (const float*)d_in[7];
    const float* beta  = (const float*)d_in[8];

    float* out  = (float*)d_out;
    float* attn = out + (long long)Bb * Ss * Dd;

    float *Qb, *Kb, *Vb, *Vt, *Cc, *Pre, *WT;
    cudaGetSymbolAddress((void**)&Qb,  g_Q);
    cudaGetSymbolAddress((void**)&Kb,  g_K);
    cudaGetSymbolAddress((void**)&Vb,  g_V);
    cudaGetSymbolAddress((void**)&Vt,  g_Vt);
    cudaGetSymbolAddress((void**)&Cc,  g_concat);
    cudaGetSymbolAddress((void**)&Pre, g_pre);
    cudaGetSymbolAddress((void**)&WT,  g_WT);

    // 0. weight transposes -> K-contig
    transpose_w_k<<<dim3(32, 32, 4), dim3(32, 8)>>>(Wq, Wk, Wv, Wo, WT);

    // 1-3. projections (M=4096, N=1024, K=1024)
    mma_gemm<128, 128, 0><<<dim3(8, 32), 256>>>(query, Dd, WT + 0ll * Dd * Dd, Dd,
                                                Qb, Dd, nullptr, 1.f, 64);
    mma_gemm<128, 128, 0><<<dim3(8, 32), 256>>>(key, Dd, WT + 1ll * Dd * Dd, Dd,
                                                Kb, Dd, nullptr, 1.f, 64);
    mma_gemm<128, 128, 0><<<dim3(8, 32), 256>>>(value, Dd, WT + 2ll * Dd * Dd, Dd,
                                                Vb, Dd, nullptr, 1.f, 64);

    // 3b. V -> Vt (K-contig for PV)
    transpose_v_k<<<dim3(32, 32, Bb), dim3(32, 8)>>>(Vb, Vt);

    // 4. causal scores: attn tiles = Q K^T / 8 (lower triangle only)
    mma_gemm<128, 128, 1><<<dim3(36, 1, Hh * Bb), 256>>>(Qb, Dd, Kb, Dd,
                                                         attn, Ss, nullptr, 0.125f, 0);

    // 5. causal softmax in place (writes the upper-triangle zeros)
    softmax_causal_k<<<Hh * Bb * Ss, 256>>>(attn);

    // 6. PV: concat tiles, K-length = (qt+1)*128
    mma_gemm<128, 64, 2><<<dim3(8, 1, Hh * Bb), 256>>>(attn, Ss, Vt, Ss,
                                                       Cc, Dd, nullptr, 1.f, 0);

    // 7. out-proj + residual
    mma_gemm<128, 128, 0><<<dim3(8, 32), 256>>>(Cc, Dd, WT + 3ll * Dd * Dd, Dd,
                                                Pre, Dd, query, 1.f, 64);

    // 8. layernorm
    layernorm_k<<<Bb * Ss, 256>>>(Pre, gamma, beta, out);
}